// round 5
// baseline (speedup 1.0000x reference)
#include <cuda_runtime.h>
#include <cuda_fp16.h>
#include <cstdint>

// Problem dims
#define M_TOTAL 8192
#define K_TOTAL 4096
#define N_TOTAL 11008

// GEMM tiling: CTA 128x256x64, 8 warps (2Mx4N), warp tile 64x64
#define TILE_M 128
#define TILE_N 256
#define TILE_K 64
#define STAGES 4
#define NUM_KT (K_TOTAL / TILE_K)     // 64
#define NT_TILES (N_TOTAL / TILE_N)   // 43
#define MT_TILES (M_TOTAL / TILE_M)   // 64
#define N_TILES (NT_TILES * MT_TILES) // 2752
#define THREADS 256
#define GRID 148                      // <= SM count; 1 CTA/SM, all co-resident

#define A_STAGE_BYTES (TILE_M * TILE_K * 2)   // 16384
#define B_STAGE_BYTES (TILE_N * TILE_K * 2)   // 32768
#define STAGE_BYTES (A_STAGE_BYTES + B_STAGE_BYTES)   // 49152
#define SMEM_BYTES (STAGES * STAGE_BYTES)             // 196608

// Scratch (device globals: allocation-free)
__device__ __align__(16) __half  g_a[(size_t)M_TOTAL * K_TOTAL];    // 67 MB fp16 input
__device__ __align__(16) uint8_t g_w8[(size_t)N_TOTAL * K_TOTAL];   // 45 MB int8 weights
__device__ unsigned int g_bar;                        // grid barrier (monotonic)

// ---------------- helpers ----------------

__device__ __forceinline__ uint32_t smem_u32(const void* p) {
    uint32_t a;
    asm("{ .reg .u64 t; cvta.to.shared.u64 t, %1; cvt.u32.u64 %0, t; }"
        : "=r"(a) : "l"(p));
    return a;
}

__device__ __forceinline__ uint32_t sw128(uint32_t off) {
    return off ^ ((off >> 3) & 0x70);
}

__device__ __forceinline__ void cp16(uint32_t dst, const void* src) {
    asm volatile("cp.async.cg.shared.global [%0], [%1], 16;"
                 :: "r"(dst), "l"(src) : "memory");
}

__device__ __forceinline__ void ldm_x4(uint32_t& r0, uint32_t& r1,
                                       uint32_t& r2, uint32_t& r3, uint32_t addr) {
    asm volatile("ldmatrix.sync.aligned.m8n8.x4.shared.b16 {%0,%1,%2,%3}, [%4];"
                 : "=r"(r0), "=r"(r1), "=r"(r2), "=r"(r3) : "r"(addr));
}

__device__ __forceinline__ void mma16816(float* c, const uint32_t* a, const uint32_t* b) {
    asm volatile(
        "mma.sync.aligned.m16n8k16.row.col.f32.f16.f16.f32 "
        "{%0,%1,%2,%3}, {%4,%5,%6,%7}, {%8,%9}, {%0,%1,%2,%3};"
        : "+f"(c[0]), "+f"(c[1]), "+f"(c[2]), "+f"(c[3])
        : "r"(a[0]), "r"(a[1]), "r"(a[2]), "r"(a[3]), "r"(b[0]), "r"(b[1]));
}

__device__ __forceinline__ uint32_t pack2f(float x, float y) {
    __half2 h = __floats2half2_rn(x, y);
    return *reinterpret_cast<uint32_t*>(&h);
}

// int8 {0,1,2} x4 -> two fp16x2 regs via PRMT LUT (exact values)
// LUT reg 0x00403C00: byte[0]=0x00 byte[1]=0x3C byte[2]=0x40 byte[3]=0x00
// half: 1.0 = 0x3C00, 2.0 = 0x4000
__device__ __forceinline__ void cvt16(uint32_t v, uint32_t& lo, uint32_t& hi) {
    uint32_t sl = ((v & 0x0303u) << 4) | 0x0303u;   // nibbles [3, b0, 3, b1]
    uint32_t sh = ((v >> 12) & 0x3030u) | 0x0303u;  // nibbles [3, b2, 3, b3]
    asm("prmt.b32 %0, %1, 0, %2;" : "=r"(lo) : "r"(0x00403C00u), "r"(sl));
    asm("prmt.b32 %0, %1, 0, %2;" : "=r"(hi) : "r"(0x00403C00u), "r"(sh));
}

// ---------------- B tile staging (int8 global -> fp16 SW128 smem) ----------------
// B stage = 256 rows x 64 int8 = 1024 x 16B chunks; 4 chunks/thread.

__device__ __forceinline__ void ldg_b(uint4* br, const uint8_t* gB, int kt, int tid) {
    const uint8_t* base = gB + kt * TILE_K;
    #pragma unroll
    for (int i = 0; i < 4; i++) {
        int c = tid + i * THREADS;
        int row = c >> 2, seg = c & 3;
        br[i] = __ldcg(reinterpret_cast<const uint4*>(base + (size_t)row * K_TOTAL + seg * 16));
    }
}

__device__ __forceinline__ void sts_b(uint32_t sB, const uint4* br, int tid) {
    #pragma unroll
    for (int i = 0; i < 4; i++) {
        int c = tid + i * THREADS;
        int row = c >> 2, seg = c & 3;
        uint32_t off = (uint32_t)(row * 128 + seg * 32);   // bit4 == 0
        uint32_t s = sB + sw128(off);
        uint32_t l0, h0, l1, h1, l2, h2, l3, h3;
        cvt16(br[i].x, l0, h0);
        cvt16(br[i].y, l1, h1);
        cvt16(br[i].z, l2, h2);
        cvt16(br[i].w, l3, h3);
        asm volatile("st.shared.v4.b32 [%0], {%1,%2,%3,%4};"
                     :: "r"(s), "r"(l0), "r"(h0), "r"(l1), "r"(h1));
        // sw128(off+16) == sw128(off) XOR 16  (NOT +16: XOR mask may set bit 4)
        asm volatile("st.shared.v4.b32 [%0], {%1,%2,%3,%4};"
                     :: "r"(s ^ 16u), "r"(l2), "r"(h2), "r"(l3), "r"(h3));
    }
}

// A stage = 128 rows x 128B fp16 = 1024 x 16B chunks; 4 cp.async/thread.
__device__ __forceinline__ void load_a(uint32_t sA, const __half* gA, int kt, int tid) {
    const __half* base = gA + kt * TILE_K;
    #pragma unroll
    for (int i = 0; i < 4; i++) {
        int c = tid + i * THREADS;
        int row = c >> 3, seg = c & 7;
        cp16(sA + sw128((uint32_t)(row * 128 + seg * 16)),
             base + (size_t)row * K_TOTAL + seg * 8);
    }
}

// ---------------- Fused persistent kernel ----------------

__global__ void __launch_bounds__(THREADS, 1)
qlinear_fused(const float* __restrict__ input,
              const int* __restrict__ qw,
              const float* __restrict__ wscale,
              const float* __restrict__ wbias,
              float* __restrict__ out) {
    extern __shared__ char smem[];
    const uint32_t sb = smem_u32(smem);
    const int tid = threadIdx.x;
    const int bid = blockIdx.x;

    // ===== Phase 1: convert (grid-strided) =====
    {
        const float4* inA = reinterpret_cast<const float4*>(input);
        uint4* outA = reinterpret_cast<uint4*>(g_a);
        const int nA = M_TOTAL * K_TOTAL / 8;   // 4194304
        for (int j = bid * THREADS + tid; j < nA; j += GRID * THREADS) {
            float4 a = inA[2 * j], b = inA[2 * j + 1];
            uint4 o;
            o.x = pack2f(a.x, a.y); o.y = pack2f(a.z, a.w);
            o.z = pack2f(b.x, b.y); o.w = pack2f(b.z, b.w);
            outA[j] = o;
        }
        const int4* inW = reinterpret_cast<const int4*>(qw);
        uint4* outW = reinterpret_cast<uint4*>(g_w8);
        const int nW = (N_TOTAL / 16) * K_TOTAL;  // 2818048 chunks of 16 ints
        for (int j = bid * THREADS + tid; j < nW; j += GRID * THREADS) {
            int4 a0 = inW[4 * j], a1 = inW[4 * j + 1], a2 = inW[4 * j + 2], a3 = inW[4 * j + 3];
            uint4 o;
            o.x = (uint32_t)a0.x | ((uint32_t)a0.y << 8) | ((uint32_t)a0.z << 16) | ((uint32_t)a0.w << 24);
            o.y = (uint32_t)a1.x | ((uint32_t)a1.y << 8) | ((uint32_t)a1.z << 16) | ((uint32_t)a1.w << 24);
            o.z = (uint32_t)a2.x | ((uint32_t)a2.y << 8) | ((uint32_t)a2.z << 16) | ((uint32_t)a2.w << 24);
            o.w = (uint32_t)a3.x | ((uint32_t)a3.y << 8) | ((uint32_t)a3.z << 16) | ((uint32_t)a3.w << 24);
            outW[j] = o;
        }
    }

    // ===== Grid barrier (generation-based: safe across graph replays) =====
    __threadfence();
    if (tid == 0) {
        unsigned a = atomicAdd(&g_bar, 1u);
        unsigned tgt = (a / GRID + 1u) * GRID;
        unsigned v;
        do {
            asm volatile("ld.acquire.gpu.u32 %0, [%1];" : "=r"(v) : "l"(&g_bar));
        } while (v < tgt);
    }
    __syncthreads();
    // GEMM reads bypass L1 (cp.async.cg / __ldcg) -> L2-coherent after barrier.

    // ===== Phase 2: persistent GEMM over tiles =====
    const int wid = tid >> 5;
    const int lid = tid & 31;
    const int warpM = wid & 1;
    const int warpN = wid >> 1;

    const int a_row = warpM * 64 + (lid & 15);
    const int a_kb  = ((lid >> 4) & 1) * 16;
    const int b_row = warpN * 64 + ((lid >> 4) & 1) * 8 + (lid & 7);
    const int b_kb  = ((lid >> 3) & 1) * 16;

    for (int t = bid; t < N_TILES; t += GRID) {
        const int nt = t % NT_TILES;
        const int mt = t / NT_TILES;
        const int m0 = mt * TILE_M;
        const int n0 = nt * TILE_N;

        const __half*  gA = g_a  + (size_t)m0 * K_TOTAL;
        const uint8_t* gB = g_w8 + (size_t)n0 * K_TOTAL;

        float acc[4][8][4];
        #pragma unroll
        for (int i = 0; i < 4; i++)
            #pragma unroll
            for (int j = 0; j < 8; j++)
                #pragma unroll
                for (int v = 0; v < 4; v++) acc[i][j][v] = 0.0f;

        // --- tile prologue ---
        uint4 br[4];
        ldg_b(br, gB, 0, tid);
        sts_b(sb + 0 * STAGE_BYTES + A_STAGE_BYTES, br, tid);   // B(0) -> stage 0
        load_a(sb + 0 * STAGE_BYTES, gA, 0, tid);
        asm volatile("cp.async.commit_group;" ::: "memory");
        load_a(sb + 1 * STAGE_BYTES, gA, 1, tid);
        asm volatile("cp.async.commit_group;" ::: "memory");
        load_a(sb + 2 * STAGE_BYTES, gA, 2, tid);
        asm volatile("cp.async.commit_group;" ::: "memory");
        ldg_b(br, gB, 1, tid);                                   // hold B(1) in regs

        for (int kt = 0; kt < NUM_KT; kt++) {
            asm volatile("cp.async.wait_group 2;" ::: "memory");
            __syncthreads();   // stage kt ready (A via wait, B via prior-iter STS)

            if (kt + 3 < NUM_KT)
                load_a(sb + ((kt + 3) % STAGES) * STAGE_BYTES, gA, kt + 3, tid);
            asm volatile("cp.async.commit_group;" ::: "memory");

            if (kt + 1 < NUM_KT)
                sts_b(sb + ((kt + 1) % STAGES) * STAGE_BYTES + A_STAGE_BYTES, br, tid);
            if (kt + 2 < NUM_KT)
                ldg_b(br, gB, kt + 2, tid);

            const uint32_t sA = sb + (kt % STAGES) * STAGE_BYTES;
            const uint32_t sB = sA + A_STAGE_BYTES;

            #pragma unroll
            for (int ks = 0; ks < 4; ks++) {
                uint32_t a[4][4];
                #pragma unroll
                for (int mi = 0; mi < 4; mi++) {
                    uint32_t off = (uint32_t)((a_row + mi * 16) * 128 + ks * 32 + a_kb);
                    ldm_x4(a[mi][0], a[mi][1], a[mi][2], a[mi][3], sA + sw128(off));
                }
                uint32_t bb[8][2];
                #pragma unroll
                for (int bj = 0; bj < 4; bj++) {
                    uint32_t t0, t1, t2, t3;
                    uint32_t off = (uint32_t)((b_row + bj * 16) * 128 + ks * 32 + b_kb);
                    ldm_x4(t0, t1, t2, t3, sB + sw128(off));
                    bb[bj * 2][0] = t0;     bb[bj * 2][1] = t1;
                    bb[bj * 2 + 1][0] = t2; bb[bj * 2 + 1][1] = t3;
                }
                #pragma unroll
                for (int mi = 0; mi < 4; mi++)
                    #pragma unroll
                    for (int ni = 0; ni < 8; ni++)
                        mma16816(acc[mi][ni], a[mi], bb[ni]);
            }
        }

        // --- epilogue: scale + bias, direct STG ---
        #pragma unroll
        for (int ni = 0; ni < 8; ni++) {
            const int col = n0 + warpN * 64 + ni * 8 + (lid & 3) * 2;
            const float2 s = *reinterpret_cast<const float2*>(wscale + col);
            const float2 b = *reinterpret_cast<const float2*>(wbias + col);
            #pragma unroll
            for (int mi = 0; mi < 4; mi++) {
                const int row = m0 + warpM * 64 + mi * 16 + (lid >> 2);
                float2 v0, v1;
                v0.x = acc[mi][ni][0] * s.x + b.x;
                v0.y = acc[mi][ni][1] * s.y + b.y;
                v1.x = acc[mi][ni][2] * s.x + b.x;
                v1.y = acc[mi][ni][3] * s.y + b.y;
                *reinterpret_cast<float2*>(out + (size_t)row * N_TOTAL + col) = v0;
                *reinterpret_cast<float2*>(out + (size_t)(row + 8) * N_TOTAL + col) = v1;
            }
        }

        __syncthreads();   // protect smem stages before next tile's prologue
    }
}

// ---------------- Launch ----------------

extern "C" void kernel_launch(void* const* d_in, const int* in_sizes, int n_in,
                              void* d_out, int out_size) {
    const float* input  = (const float*)d_in[0];   // [8192, 4096] fp32
    const int*   qw     = (const int*)d_in[1];     // [11008, 4096] int32 in {0,1,2}
    const float* wscale = (const float*)d_in[2];   // [11008]
    const float* wbias  = (const float*)d_in[3];   // [11008]
    float* out = (float*)d_out;                    // [8192, 11008] fp32

    cudaFuncSetAttribute(qlinear_fused,
                         cudaFuncAttributeMaxDynamicSharedMemorySize, SMEM_BYTES);
    qlinear_fused<<<GRID, THREADS, SMEM_BYTES>>>(input, qw, wscale, wbias, out);
}

// round 6
// speedup vs baseline: 1.3262x; 1.3262x over previous
#include <cuda_runtime.h>
#include <cuda_fp16.h>
#include <cstdint>

// Problem dims
#define M_TOTAL 8192
#define K_TOTAL 4096
#define N_TOTAL 11008

// GEMM tiling: CTA 128x128x64, 8 warps (2M x 4N), warp tile 64x32
#define TILE_M 128
#define TILE_N 128
#define TILE_K 64
#define STAGES 3
#define NUM_KT (K_TOTAL / TILE_K)     // 64
#define NT_TILES (N_TOTAL / TILE_N)   // 86
#define MT_TILES (M_TOTAL / TILE_M)   // 64
#define THREADS 256

#define A_STAGE_BYTES (TILE_M * TILE_K * 2)   // 16384
#define B_STAGE_BYTES (TILE_N * TILE_K * 2)   // 16384
#define STAGE_BYTES (A_STAGE_BYTES + B_STAGE_BYTES)   // 32768
#define SMEM_BYTES (STAGES * STAGE_BYTES)             // 98304 -> 2 CTAs/SM

// fp16 scratch (device globals: allocation-free scratch)
__device__ __align__(16) __half g_a[(size_t)M_TOTAL * K_TOTAL];   // 67 MB
__device__ __align__(16) __half g_w[(size_t)N_TOTAL * K_TOTAL];   // 90 MB

// ---------------- helpers ----------------

__device__ __forceinline__ uint32_t smem_u32(const void* p) {
    uint32_t a;
    asm("{ .reg .u64 t; cvta.to.shared.u64 t, %1; cvt.u32.u64 %0, t; }"
        : "=r"(a) : "l"(p));
    return a;
}

__device__ __forceinline__ uint32_t sw128(uint32_t off) {
    return off ^ ((off >> 3) & 0x70);
}

__device__ __forceinline__ void cp16(uint32_t dst, const void* src) {
    asm volatile("cp.async.cg.shared.global [%0], [%1], 16;"
                 :: "r"(dst), "l"(src) : "memory");
}

__device__ __forceinline__ void ldm_x4(uint32_t& r0, uint32_t& r1,
                                       uint32_t& r2, uint32_t& r3, uint32_t addr) {
    asm volatile("ldmatrix.sync.aligned.m8n8.x4.shared.b16 {%0,%1,%2,%3}, [%4];"
                 : "=r"(r0), "=r"(r1), "=r"(r2), "=r"(r3) : "r"(addr));
}

__device__ __forceinline__ void mma16816(float* c, const uint32_t* a, const uint32_t* b) {
    asm volatile(
        "mma.sync.aligned.m16n8k16.row.col.f32.f16.f16.f32 "
        "{%0,%1,%2,%3}, {%4,%5,%6,%7}, {%8,%9}, {%0,%1,%2,%3};"
        : "+f"(c[0]), "+f"(c[1]), "+f"(c[2]), "+f"(c[3])
        : "r"(a[0]), "r"(a[1]), "r"(a[2]), "r"(a[3]), "r"(b[0]), "r"(b[1]));
}

// ---------------- Conversion kernels ----------------

__device__ __forceinline__ uint32_t pack2f(float x, float y) {
    __half2 h = __floats2half2_rn(x, y);
    return *reinterpret_cast<uint32_t*>(&h);
}
__device__ __forceinline__ uint32_t pack2i(int x, int y) {
    __half2 h = __halves2half2(__int2half_rn(x), __int2half_rn(y));
    return *reinterpret_cast<uint32_t*>(&h);
}

__global__ void convert_input_k(const float4* __restrict__ in, uint4* __restrict__ out) {
    int i = blockIdx.x * blockDim.x + threadIdx.x;
    float4 a = in[2 * i];
    float4 b = in[2 * i + 1];
    uint4 o;
    o.x = pack2f(a.x, a.y);
    o.y = pack2f(a.z, a.w);
    o.z = pack2f(b.x, b.y);
    o.w = pack2f(b.z, b.w);
    out[i] = o;
}

__global__ void convert_weight_k(const int4* __restrict__ in, uint4* __restrict__ out) {
    int i = blockIdx.x * blockDim.x + threadIdx.x;
    int4 a = in[2 * i];
    int4 b = in[2 * i + 1];
    uint4 o;
    o.x = pack2i(a.x, a.y);
    o.y = pack2i(a.z, a.w);
    o.z = pack2i(b.x, b.y);
    o.w = pack2i(b.z, b.w);
    out[i] = o;
}

// ---------------- GEMM kernel ----------------
// 256 threads = 8 warps in a 2(M) x 4(N) grid. Warp tile: 64(M) x 32(N).
// acc = 64 regs/thread -> fits 2 CTAs/SM at <=128 regs.

__device__ __forceinline__ void load_stage(uint32_t sb, int stage, int kt,
                                           const __half* gA, const __half* gB, int tid) {
    uint32_t sA = sb + stage * STAGE_BYTES;
    uint32_t sB = sA + A_STAGE_BYTES;
    const __half* pa = gA + kt * TILE_K;
    const __half* pb = gB + kt * TILE_K;
    // A: 128 rows x 128B = 1024 16B-chunks -> 4 per thread
    #pragma unroll
    for (int i = 0; i < 4; i++) {
        int idx = tid + i * THREADS;
        int row = idx >> 3, c = idx & 7;
        cp16(sA + sw128((uint32_t)(row * 128 + c * 16)),
             pa + (size_t)row * K_TOTAL + c * 8);
    }
    // B: 128 rows x 128B = 1024 16B-chunks -> 4 per thread
    #pragma unroll
    for (int i = 0; i < 4; i++) {
        int idx = tid + i * THREADS;
        int row = idx >> 3, c = idx & 7;
        cp16(sB + sw128((uint32_t)(row * 128 + c * 16)),
             pb + (size_t)row * K_TOTAL + c * 8);
    }
}

__global__ void __launch_bounds__(THREADS, 2)
qlinear_gemm(const float* __restrict__ wscale,
             const float* __restrict__ wbias,
             float* __restrict__ out) {
    extern __shared__ char smem[];
    const uint32_t sb = smem_u32(smem);
    const int tid = threadIdx.x;
    const int wid = tid >> 5;
    const int lid = tid & 31;
    const int warpM = wid & 1;   // 0..1 -> M offset warpM*64
    const int warpN = wid >> 1;  // 0..3 -> N offset warpN*32

    // M fastest: for a fixed n-column, the W panel (1 MB) + all of A stay L2-hot
    const int mt = blockIdx.x % MT_TILES;
    const int nt = blockIdx.x / MT_TILES;
    const int m0 = mt * TILE_M;
    const int n0 = nt * TILE_N;

    const __half* gA = g_a + (size_t)m0 * K_TOTAL;
    const __half* gB = g_w + (size_t)n0 * K_TOTAL;

    float acc[4][4][4];
    #pragma unroll
    for (int i = 0; i < 4; i++)
        #pragma unroll
        for (int j = 0; j < 4; j++)
            #pragma unroll
            for (int v = 0; v < 4; v++) acc[i][j][v] = 0.0f;

    // ldmatrix lane addressing
    const int a_row = warpM * 64 + (lid & 15);
    const int a_kb  = ((lid >> 4) & 1) * 16;
    const int b_row = warpN * 32 + ((lid >> 4) & 1) * 8 + (lid & 7);
    const int b_kb  = ((lid >> 3) & 1) * 16;

    // Prologue: stages 0,1
    load_stage(sb, 0, 0, gA, gB, tid);
    asm volatile("cp.async.commit_group;" ::: "memory");
    load_stage(sb, 1, 1, gA, gB, tid);
    asm volatile("cp.async.commit_group;" ::: "memory");

    for (int kt = 0; kt < NUM_KT; kt++) {
        asm volatile("cp.async.wait_group 1;" ::: "memory");
        __syncthreads();

        if (kt + 2 < NUM_KT) {
            load_stage(sb, (kt + 2) % STAGES, kt + 2, gA, gB, tid);
        }
        asm volatile("cp.async.commit_group;" ::: "memory");

        const uint32_t sA = sb + (kt % STAGES) * STAGE_BYTES;
        const uint32_t sB = sA + A_STAGE_BYTES;

        #pragma unroll
        for (int ks = 0; ks < 4; ks++) {
            uint32_t a[4][4];
            #pragma unroll
            for (int mi = 0; mi < 4; mi++) {
                uint32_t off = (uint32_t)((a_row + mi * 16) * 128 + ks * 32 + a_kb);
                ldm_x4(a[mi][0], a[mi][1], a[mi][2], a[mi][3], sA + sw128(off));
            }
            uint32_t bb[4][2];
            #pragma unroll
            for (int bj = 0; bj < 2; bj++) {
                uint32_t t0, t1, t2, t3;
                uint32_t off = (uint32_t)((b_row + bj * 16) * 128 + ks * 32 + b_kb);
                ldm_x4(t0, t1, t2, t3, sB + sw128(off));
                bb[bj * 2][0] = t0;     bb[bj * 2][1] = t1;
                bb[bj * 2 + 1][0] = t2; bb[bj * 2 + 1][1] = t3;
            }
            #pragma unroll
            for (int mi = 0; mi < 4; mi++)
                #pragma unroll
                for (int ni = 0; ni < 4; ni++)
                    mma16816(acc[mi][ni], a[mi], bb[ni]);
        }

        __syncthreads();   // protect stage (kt+2)%3 == (kt-1)%3 writes vs readers
    }

    // Epilogue: direct STG with per-column scale + bias
    #pragma unroll
    for (int ni = 0; ni < 4; ni++) {
        const int col = n0 + warpN * 32 + ni * 8 + (lid & 3) * 2;
        const float2 s = *reinterpret_cast<const float2*>(wscale + col);
        const float2 b = *reinterpret_cast<const float2*>(wbias + col);
        #pragma unroll
        for (int mi = 0; mi < 4; mi++) {
            const int row = m0 + warpM * 64 + mi * 16 + (lid >> 2);
            float2 v0, v1;
            v0.x = acc[mi][ni][0] * s.x + b.x;
            v0.y = acc[mi][ni][1] * s.y + b.y;
            v1.x = acc[mi][ni][2] * s.x + b.x;
            v1.y = acc[mi][ni][3] * s.y + b.y;
            *reinterpret_cast<float2*>(out + (size_t)row * N_TOTAL + col) = v0;
            *reinterpret_cast<float2*>(out + (size_t)(row + 8) * N_TOTAL + col) = v1;
        }
    }
}

// ---------------- Launch ----------------

extern "C" void kernel_launch(void* const* d_in, const int* in_sizes, int n_in,
                              void* d_out, int out_size) {
    const float* input  = (const float*)d_in[0];   // [8192, 4096] fp32
    const int*   qw     = (const int*)d_in[1];     // [11008, 4096] int32 in {0,1,2}
    const float* wscale = (const float*)d_in[2];   // [11008]
    const float* wbias  = (const float*)d_in[3];   // [11008]
    float* out = (float*)d_out;                    // [8192, 11008] fp32

    void* pa = nullptr;
    void* pw = nullptr;
    cudaGetSymbolAddress(&pa, g_a);
    cudaGetSymbolAddress(&pw, g_w);

    convert_input_k<<<16384, 256>>>((const float4*)input, (uint4*)pa);
    convert_weight_k<<<22016, 256>>>((const int4*)qw, (uint4*)pw);

    cudaFuncSetAttribute(qlinear_gemm,
                         cudaFuncAttributeMaxDynamicSharedMemorySize, SMEM_BYTES);
    qlinear_gemm<<<MT_TILES * NT_TILES, THREADS, SMEM_BYTES>>>(wscale, wbias, out);
}